// round 12
// baseline (speedup 1.0000x reference)
#include <cuda_runtime.h>
#include <math.h>

// ---------------------------------------------------------------------------
// FocalLoss (RetinaNet-style) on GB300 — single-wave, evenly-balanced fused
// kernel (R6 skeleton + L2::256B prefetch + perfect partition).
//  Part 1 (match, grid-stride over anchors):
//      matched  -> reg smooth-L1, count, gt-element pos-correction
//      deadzone -> cancel own clf row's stream contribution (exact formula)
//  Part 2 (stream): each block owns one contiguous chunk (identical size);
//      full 4096-float4 tiles use an unrolled fast path with
//      ld.global.nc.L2::256B loads;  acc += pm^2*log2(1-pm), pm=min(p,1-eps);
//      scaled once by -0.75*ln2.
//  Part 3: ticket; last block finalizes outputs and resets state.
// Inputs (metadata order):
//   d_in[0] classifications float32 [B, A, C]
//   d_in[1] regressions     float32 [B, A, 4]
//   d_in[2] anchors         float32 [1, A, 4]   (y1, x1, y2, x2)
//   d_in[3] annotations     float32 [B, M, 5]   (x1, y1, x2, y2, label)
// Output: float32 [2] = (clf_loss_weighted, reg_loss_weighted)
// ---------------------------------------------------------------------------

#define FL_EPS    1e-4f
#define MAX_B     16
#define MAX_M     128
#define LN2_D     0.693147180559945309
#define THREADS   256
#define TILE_K    16
#define TILE_V4   (THREADS * TILE_K)     // 4096 float4 = 64 KB

__device__ double g_clf_sum[MAX_B];
__device__ double g_sl1_sum[MAX_B];
__device__ int    g_nm[MAX_B];
__device__ unsigned int g_ticket;    // zero-init; self-resetting each replay

// identical per-element core used by stream AND all corrections
__device__ __forceinline__ float fl_core(float p) {
    const float pm = fminf(p, 1.0f - FL_EPS);
    return pm * pm * __log2f(1.0f - pm);      // negative
}

// 128B load with 256B L2 fill hint (read-only path)
__device__ __forceinline__ float4 ldg_pf256(const float4* p) {
    float4 v;
    asm("ld.global.nc.L2::256B.v4.f32 {%0,%1,%2,%3}, [%4];"
        : "=f"(v.x), "=f"(v.y), "=f"(v.z), "=f"(v.w) : "l"(p));
    return v;
}

__global__ __launch_bounds__(THREADS, 8)
void fl_fused_kernel(const float4* __restrict__ clf4,
                     const float*  __restrict__ clf,
                     const float4* __restrict__ reg,
                     const float4* __restrict__ anc,
                     const float*  __restrict__ ann,
                     float* __restrict__ out,
                     int A, int C, int B, int M, int perImgV4) {
    const int b = blockIdx.y;

    __shared__ float  s_raw[MAX_M * 5];
    __shared__ float  s_bx1[MAX_M], s_by1[MAX_M], s_bx2[MAX_M], s_by2[MAX_M];
    __shared__ float  s_bar[MAX_M], s_lbl[MAX_M];
    __shared__ int    s_nv;
    __shared__ double s_sl1, s_cor, s_acc;
    __shared__ int    s_nm;
    __shared__ bool   s_last;

    if (threadIdx.x == 0) { s_sl1 = 0.0; s_cor = 0.0; s_acc = 0.0; s_nm = 0; }
    {
        const int annN = M * 5;
        for (int i = threadIdx.x; i < annN; i += blockDim.x)
            s_raw[i] = ann[(size_t)b * annN + i];
    }
    __syncthreads();
    if (threadIdx.x == 0) {
        int nv = 0;
        for (int j = 0; j < M; j++) {
            const float lbl = s_raw[j * 5 + 4];
            if (lbl == -1.0f) continue;             // order preserved -> tiebreak ok
            s_bx1[nv] = s_raw[j * 5 + 0];
            s_by1[nv] = s_raw[j * 5 + 1];
            s_bx2[nv] = s_raw[j * 5 + 2];
            s_by2[nv] = s_raw[j * 5 + 3];
            s_bar[nv] = (s_bx2[nv] - s_bx1[nv]) * (s_by2[nv] - s_by1[nv]);
            s_lbl[nv] = lbl;
            nv++;
        }
        s_nv = nv;
    }
    __syncthreads();

    // ============== Part 1: matching (grid-stride over anchors) ============
    {
        const int tstride = gridDim.x * blockDim.x;
        const int nv = s_nv;
        for (int a = blockIdx.x * blockDim.x + threadIdx.x; a < A; a += tstride) {
            const float4 av = anc[a];            // y1, x1, y2, x2
            const float ay1 = av.x, ax1 = av.y, ay2 = av.z, ax2 = av.w;
            const float aarea = (ax2 - ax1) * (ay2 - ay1);

            // division-free argmax over valid boxes (first-index tiebreak)
            float bestI = 0.0f, bestU = 1.0f;
            int   idx = -1;
            for (int j = 0; j < nv; j++) {
                float iw = fminf(ax2, s_bx2[j]) - fmaxf(ax1, s_bx1[j]); iw = fmaxf(iw, 0.0f);
                float ih = fminf(ay2, s_by2[j]) - fmaxf(ay1, s_by1[j]); ih = fmaxf(ih, 0.0f);
                const float inter = iw * ih;
                const float uni = fmaxf(aarea + s_bar[j] - inter, 1e-8f);
                if (idx < 0) { bestI = inter; bestU = uni; idx = j; }
                else if (inter * bestU > bestI * uni) { bestI = inter; bestU = uni; idx = j; }
            }
            const float v = (idx >= 0) ? (bestI / bestU) : -1.0f;
            const bool matched   = v > 0.5f;
            const bool unmatched = v < 0.4f;

            if (!matched && !unmatched) {
                // dead-zone: cancel this row's stream contribution
                const float* row = clf + ((size_t)b * A + a) * C;
                float s = 0.0f;
                for (int c = 0; c < C; c++) s += fl_core(row[c]);
                atomicAdd(&s_cor, (double)s * (0.75 * LN2_D));
            } else if (matched) {
                // gt-element correction: replace stream's neg term by pos term
                const int gt = (int)s_lbl[idx] - 1;
                const float p = clf[((size_t)b * A + a) * C + gt];
                const float pc = fminf(fmaxf(p, FL_EPS), 1.0f - FL_EPS);
                const float om = 1.0f - pc;
                const double pos = (double)(0.25f * om * om * (-__logf(pc)));
                const double st  = (double)fl_core(p) * (-0.75 * LN2_D);
                atomicAdd(&s_cor, pos - st);

                // regression smooth-L1
                const float gx1 = s_bx1[idx], gy1 = s_by1[idx];
                const float gx2 = s_bx2[idx], gy2 = s_by2[idx];
                const float gwr = gx2 - gx1, ghr = gy2 - gy1;
                const float gcx = gx1 + 0.5f * gwr, gcy = gy1 + 0.5f * ghr;
                const float gw = fmaxf(gwr, 1.0f),  gh = fmaxf(ghr, 1.0f);
                const float aw = ax2 - ax1, ah = ay2 - ay1;
                const float acx = ax1 + 0.5f * aw, acy = ay1 + 0.5f * ah;
                const float4 rv = reg[(size_t)b * A + a];
                float s = 0.0f;
                float d;
                d = fabsf(9.0f * (rv.x - (gcy - acy) / ah));
                s += (d < 1.0f) ? 0.5f * d * d : (d - 0.5f);
                d = fabsf(9.0f * (rv.y - (gcx - acx) / aw));
                s += (d < 1.0f) ? 0.5f * d * d : (d - 0.5f);
                d = fabsf(9.0f * (rv.z - __logf(gh / ah)));
                s += (d < 1.0f) ? 0.5f * d * d : (d - 0.5f);
                d = fabsf(9.0f * (rv.w - __logf(gw / aw)));
                s += (d < 1.0f) ? 0.5f * d * d : (d - 0.5f);
                atomicAdd(&s_sl1, (double)s);
                atomicAdd(&s_nm, 1);
            }
        }
    }

    // ========= Part 2: even contiguous chunks, prefetch-hinted tiles =======
    {
        const float4* base = clf4 + (size_t)b * perImgV4;
        const int chunk = (perImgV4 + gridDim.x - 1) / gridDim.x;  // identical/block
        const int start = blockIdx.x * chunk;
        const int end   = min(start + chunk, perImgV4);

        float acc0 = 0.0f, acc1 = 0.0f;
        for (int t0 = start; t0 < end; t0 += TILE_V4) {
            if (t0 + TILE_V4 <= end) {
                const float4* p = base + t0 + threadIdx.x;
                #pragma unroll
                for (int k = 0; k < TILE_K; k++) {
                    const float4 v = ldg_pf256(p + k * THREADS);
                    acc0 += fl_core(v.x) + fl_core(v.y);
                    acc1 += fl_core(v.z) + fl_core(v.w);
                }
            } else {
                for (int i = t0 + threadIdx.x; i < end; i += THREADS) {
                    const float4 v = base[i];
                    acc0 += fl_core(v.x) + fl_core(v.y);
                    acc1 += fl_core(v.z) + fl_core(v.w);
                }
            }
        }
        float acc = acc0 + acc1;
        if (blockIdx.x == 0 && threadIdx.x == 0) {     // scalar tail, if any
            for (int e = perImgV4 * 4; e < A * C; e++)
                acc += fl_core(clf[(size_t)b * A * C + e]);
        }
        #pragma unroll
        for (int off = 16; off; off >>= 1)
            acc += __shfl_xor_sync(0xffffffffu, acc, off);
        if ((threadIdx.x & 31) == 0)
            atomicAdd(&s_acc, (double)acc);
    }
    __syncthreads();

    // ======================= Part 3: accumulate + finalize =================
    if (threadIdx.x == 0) {
        const double clfAdd = s_acc * (-0.75 * LN2_D) + s_cor;
        if (clfAdd != 0.0) atomicAdd(&g_clf_sum[b], clfAdd);
        if (s_sl1 != 0.0)  atomicAdd(&g_sl1_sum[b], s_sl1);
        if (s_nm)          atomicAdd(&g_nm[b], s_nm);
        __threadfence();
        const unsigned int total = gridDim.x * gridDim.y;
        const unsigned int t = atomicAdd(&g_ticket, 1u);
        s_last = (t == total - 1u);
    }
    __syncthreads();

    if (s_last && threadIdx.x == 0) {
        __threadfence();
        double cl = 0.0, rl = 0.0;
        for (int bb = 0; bb < B; bb++) {
            const int nm = g_nm[bb];
            const int dn = nm > 1 ? nm : 1;
            cl += g_clf_sum[bb] / (double)dn;
            if (nm > 0) rl += g_sl1_sum[bb] / (double)(4 * nm);
            g_clf_sum[bb] = 0.0;
            g_sl1_sum[bb] = 0.0;
            g_nm[bb]      = 0;
        }
        out[0] = (float)(cl / (double)B);          // CLF_W = 1.0
        out[1] = (float)(50.0 * rl / (double)B);   // REG_W = 50.0
        g_ticket = 0u;
    }
}

extern "C" void kernel_launch(void* const* d_in, const int* in_sizes, int n_in,
                              void* d_out, int out_size) {
    const float* clf = (const float*)d_in[0];
    const float* reg = (const float*)d_in[1];
    const float* anc = (const float*)d_in[2];
    const float* ann = (const float*)d_in[3];
    float* out = (float*)d_out;

    const int A = in_sizes[2] / 4;                       // anchors: 1*A*4
    const int B = in_sizes[1] / (4 * A);                 // regressions: B*A*4
    const int C = (int)((long long)in_sizes[0] / ((long long)B * A)); // B*A*C
    const int M = in_sizes[3] / (5 * B);                 // annotations: B*M*5

    const int perImgV4 = (A * C) / 4;
    // exactly one wave: 152 SMs x 8 CTAs/SM = 1216 blocks = gridX * B
    int blocksX = (8 * 152) / (B > 0 ? B : 1);
    if (blocksX < 1) blocksX = 1;
    if (blocksX > perImgV4) blocksX = perImgV4 > 0 ? perImgV4 : 1;
    dim3 grid(blocksX, B);
    fl_fused_kernel<<<grid, THREADS>>>((const float4*)clf, clf,
                                       (const float4*)reg, (const float4*)anc,
                                       ann, out, A, C, B, M, perImgV4);
}

// round 13
// speedup vs baseline: 1.1952x; 1.1952x over previous
#include <cuda_runtime.h>
#include <math.h>

// ---------------------------------------------------------------------------
// FocalLoss (RetinaNet-style) on GB300 — single fused kernel, tile streaming.
// (Round-6 configuration: empirical optimum over 12 structural variants.)
//  - First blocks per image do per-anchor matching:
//      * matched: reg smooth-L1, count, gt-element pos-correction
//      * dead-zone: cancel own clf row's stream contribution (exact formula)
//  - All blocks stream the clf tensor over CONTIGUOUS 64KB tiles
//      (256 thr x 16 float4, 4-way load batching 4KB apart -> page-local):
//      acc += p'^2 * log2(1-p'),  scaled once by -0.75*ln2.
//  - Ticket: last block finalizes the two outputs and resets state.
// Inputs (metadata order):
//   d_in[0] classifications float32 [B, A, C]
//   d_in[1] regressions     float32 [B, A, 4]
//   d_in[2] anchors         float32 [1, A, 4]   (y1, x1, y2, x2)
//   d_in[3] annotations     float32 [B, M, 5]   (x1, y1, x2, y2, label)
// Output: float32 [2] = (clf_loss_weighted, reg_loss_weighted)
// ---------------------------------------------------------------------------

#define FL_EPS    1e-4f
#define MAX_B     16
#define MAX_M     128
#define LN2_D     0.693147180559945309
#define TILE_K    16                      // float4 per thread per tile
#define THREADS   256
#define TILE_V4   (THREADS * TILE_K)      // 4096 float4 = 64KB

__device__ double g_clf_sum[MAX_B];
__device__ double g_sl1_sum[MAX_B];
__device__ int    g_nm[MAX_B];
__device__ unsigned int g_ticket;    // zero-init; self-resetting each replay

// identical per-element core used by stream AND all corrections
__device__ __forceinline__ float fl_core(float p) {
    const float pm = fminf(p, 1.0f - FL_EPS);
    return pm * pm * __log2f(1.0f - pm);      // negative
}

__global__ __launch_bounds__(THREADS, 8)
void fl_fused_kernel(const float4* __restrict__ clf4,
                     const float*  __restrict__ clf,
                     const float4* __restrict__ reg,
                     const float4* __restrict__ anc,
                     const float*  __restrict__ ann,
                     float* __restrict__ out,
                     int A, int C, int B, int M, int perImgV4) {
    const int b = blockIdx.y;
    const int a = blockIdx.x * blockDim.x + threadIdx.x;

    __shared__ float  s_raw[MAX_M * 5];
    __shared__ float  s_bx1[MAX_M], s_by1[MAX_M], s_bx2[MAX_M], s_by2[MAX_M];
    __shared__ float  s_bar[MAX_M], s_lbl[MAX_M];
    __shared__ int    s_nv;
    __shared__ double s_sl1, s_cor, s_acc;
    __shared__ int    s_nm;
    __shared__ bool   s_last;

    const bool blockHasAnchors = (blockIdx.x * blockDim.x) < A;

    if (threadIdx.x == 0) { s_sl1 = 0.0; s_cor = 0.0; s_acc = 0.0; s_nm = 0; }
    if (blockHasAnchors) {
        const int annN = M * 5;
        for (int i = threadIdx.x; i < annN; i += blockDim.x)
            s_raw[i] = ann[(size_t)b * annN + i];
    }
    __syncthreads();
    if (blockHasAnchors && threadIdx.x == 0) {
        int nv = 0;
        for (int j = 0; j < M; j++) {
            const float lbl = s_raw[j * 5 + 4];
            if (lbl == -1.0f) continue;             // order preserved -> tiebreak ok
            const float bx1 = s_raw[j * 5 + 0];
            const float by1 = s_raw[j * 5 + 1];
            const float bx2 = s_raw[j * 5 + 2];
            const float by2 = s_raw[j * 5 + 3];
            s_bx1[nv] = bx1; s_by1[nv] = by1;
            s_bx2[nv] = bx2; s_by2[nv] = by2;
            s_bar[nv] = (bx2 - bx1) * (by2 - by1);
            s_lbl[nv] = lbl;
            nv++;
        }
        s_nv = nv;
    }
    __syncthreads();

    // ======================= Part 1: matching ==============================
    if (blockHasAnchors && a < A) {
        const float4 av = anc[a];            // y1, x1, y2, x2
        const float ay1 = av.x, ax1 = av.y, ay2 = av.z, ax2 = av.w;
        const float aarea = (ax2 - ax1) * (ay2 - ay1);
        const int nv = s_nv;

        // division-free argmax over valid boxes (first-index tiebreak kept)
        float bestI = 0.0f, bestU = 1.0f;
        int   idx = -1;
        for (int j = 0; j < nv; j++) {
            float iw = fminf(ax2, s_bx2[j]) - fmaxf(ax1, s_bx1[j]); iw = fmaxf(iw, 0.0f);
            float ih = fminf(ay2, s_by2[j]) - fmaxf(ay1, s_by1[j]); ih = fmaxf(ih, 0.0f);
            const float inter = iw * ih;
            const float uni = fmaxf(aarea + s_bar[j] - inter, 1e-8f);
            if (idx < 0) { bestI = inter; bestU = uni; idx = j; }
            else if (inter * bestU > bestI * uni) { bestI = inter; bestU = uni; idx = j; }
        }
        const float v = (idx >= 0) ? (bestI / bestU) : -1.0f;
        const bool matched   = v > 0.5f;
        const bool unmatched = v < 0.4f;

        if (!matched && !unmatched) {
            // dead-zone: cancel this row's stream contribution (exact formula)
            const float* row = clf + ((size_t)b * A + a) * C;
            float s = 0.0f;
            for (int c = 0; c < C; c++) s += fl_core(row[c]);
            atomicAdd(&s_cor, (double)s * (0.75 * LN2_D));
        } else if (matched) {
            // gt-element correction: replace stream's neg term with pos term
            const int gt = (int)s_lbl[idx] - 1;
            const float p = clf[((size_t)b * A + a) * C + gt];
            const float pc = fminf(fmaxf(p, FL_EPS), 1.0f - FL_EPS);
            const float om = 1.0f - pc;
            const double pos = (double)(0.25f * om * om * (-__logf(pc)));
            const double st  = (double)fl_core(p) * (-0.75 * LN2_D);
            atomicAdd(&s_cor, pos - st);

            // regression smooth-L1
            const float gx1 = s_bx1[idx], gy1 = s_by1[idx];
            const float gx2 = s_bx2[idx], gy2 = s_by2[idx];
            const float gwr = gx2 - gx1, ghr = gy2 - gy1;
            const float gcx = gx1 + 0.5f * gwr, gcy = gy1 + 0.5f * ghr;
            const float gw = fmaxf(gwr, 1.0f),  gh = fmaxf(ghr, 1.0f);
            const float aw = ax2 - ax1, ah = ay2 - ay1;
            const float acx = ax1 + 0.5f * aw, acy = ay1 + 0.5f * ah;
            const float4 rv = reg[(size_t)b * A + a];
            float s = 0.0f;
            float d;
            d = fabsf(9.0f * (rv.x - (gcy - acy) / ah));
            s += (d < 1.0f) ? 0.5f * d * d : (d - 0.5f);
            d = fabsf(9.0f * (rv.y - (gcx - acx) / aw));
            s += (d < 1.0f) ? 0.5f * d * d : (d - 0.5f);
            d = fabsf(9.0f * (rv.z - __logf(gh / ah)));
            s += (d < 1.0f) ? 0.5f * d * d : (d - 0.5f);
            d = fabsf(9.0f * (rv.w - __logf(gw / aw)));
            s += (d < 1.0f) ? 0.5f * d * d : (d - 0.5f);
            atomicAdd(&s_sl1, (double)s);
            atomicAdd(&s_nm, 1);
        }
    }

    // ================= Part 2: contiguous-tile stream ======================
    {
        const float4* base = clf4 + (size_t)b * perImgV4;
        const int ntiles = (perImgV4 + TILE_V4 - 1) / TILE_V4;
        float acc0 = 0.0f, acc1 = 0.0f;
        for (int t = blockIdx.x; t < ntiles; t += gridDim.x) {
            const int i0 = t * TILE_V4 + threadIdx.x;
            if (t * TILE_V4 + TILE_V4 <= perImgV4) {
                // full tile: unguarded, 4-way batched loads 4KB apart
                #pragma unroll
                for (int k = 0; k < TILE_K; k += 4) {
                    const float4 v0 = base[i0 + (k + 0) * THREADS];
                    const float4 v1 = base[i0 + (k + 1) * THREADS];
                    const float4 v2 = base[i0 + (k + 2) * THREADS];
                    const float4 v3 = base[i0 + (k + 3) * THREADS];
                    acc0 += fl_core(v0.x) + fl_core(v0.y);
                    acc1 += fl_core(v0.z) + fl_core(v0.w);
                    acc0 += fl_core(v1.x) + fl_core(v1.y);
                    acc1 += fl_core(v1.z) + fl_core(v1.w);
                    acc0 += fl_core(v2.x) + fl_core(v2.y);
                    acc1 += fl_core(v2.z) + fl_core(v2.w);
                    acc0 += fl_core(v3.x) + fl_core(v3.y);
                    acc1 += fl_core(v3.z) + fl_core(v3.w);
                }
            } else {
                for (int k = 0; k < TILE_K; k++) {
                    const int ii = i0 + k * THREADS;
                    if (ii < perImgV4) {
                        const float4 v = base[ii];
                        acc0 += fl_core(v.x) + fl_core(v.y);
                        acc1 += fl_core(v.z) + fl_core(v.w);
                    }
                }
            }
        }
        float acc = acc0 + acc1;
        if (blockIdx.x == 0 && threadIdx.x == 0) {     // scalar tail, if any
            for (int e = perImgV4 * 4; e < A * C; e++)
                acc += fl_core(clf[(size_t)b * A * C + e]);
        }
        #pragma unroll
        for (int off = 16; off; off >>= 1)
            acc += __shfl_xor_sync(0xffffffffu, acc, off);
        if ((threadIdx.x & 31) == 0)
            atomicAdd(&s_acc, (double)acc);
    }
    __syncthreads();

    // ======================= Part 3: accumulate + finalize =================
    if (threadIdx.x == 0) {
        const double clfAdd = s_acc * (-0.75 * LN2_D) + s_cor;
        if (clfAdd != 0.0) atomicAdd(&g_clf_sum[b], clfAdd);
        if (s_sl1 != 0.0)  atomicAdd(&g_sl1_sum[b], s_sl1);
        if (s_nm)          atomicAdd(&g_nm[b], s_nm);
        __threadfence();
        const unsigned int total = gridDim.x * gridDim.y;
        const unsigned int t = atomicAdd(&g_ticket, 1u);
        s_last = (t == total - 1u);
    }
    __syncthreads();

    if (s_last && threadIdx.x == 0) {
        __threadfence();
        double cl = 0.0, rl = 0.0;
        for (int bb = 0; bb < B; bb++) {
            const int nm = g_nm[bb];
            const int dn = nm > 1 ? nm : 1;
            cl += g_clf_sum[bb] / (double)dn;
            if (nm > 0) rl += g_sl1_sum[bb] / (double)(4 * nm);
            g_clf_sum[bb] = 0.0;
            g_sl1_sum[bb] = 0.0;
            g_nm[bb]      = 0;
        }
        out[0] = (float)(cl / (double)B);          // CLF_W = 1.0
        out[1] = (float)(50.0 * rl / (double)B);   // REG_W = 50.0
        g_ticket = 0u;
    }
}

extern "C" void kernel_launch(void* const* d_in, const int* in_sizes, int n_in,
                              void* d_out, int out_size) {
    const float* clf = (const float*)d_in[0];
    const float* reg = (const float*)d_in[1];
    const float* anc = (const float*)d_in[2];
    const float* ann = (const float*)d_in[3];
    float* out = (float*)d_out;

    const int A = in_sizes[2] / 4;                       // anchors: 1*A*4
    const int B = in_sizes[1] / (4 * A);                 // regressions: B*A*4
    const int C = (int)((long long)in_sizes[0] / ((long long)B * A)); // B*A*C
    const int M = in_sizes[3] / (5 * B);                 // annotations: B*M*5

    const int perImgV4 = (A * C) / 4;
    const int ntiles = (perImgV4 + TILE_V4 - 1) / TILE_V4;
    const int needX  = (A + THREADS - 1) / THREADS;      // cover all anchors
    int blocksX = ntiles;                                 // one tile per block pass
    if (blocksX < needX) blocksX = needX;
    if (blocksX < 1) blocksX = 1;
    dim3 grid(blocksX, B);
    fl_fused_kernel<<<grid, THREADS>>>((const float4*)clf, clf,
                                       (const float4*)reg, (const float4*)anc,
                                       ann, out, A, C, B, M, perImgV4);
}